// round 5
// baseline (speedup 1.0000x reference)
#include <cuda_runtime.h>
#include <cstdint>

// SINDy_SHRED: 10 Euler steps of z += Theta(z) @ (C*mask) * dt
// per (sample, replicate). Theta = [1, z, z_i z_j (i<=j), sin(z)] -> 169 rows.
//
// R5 == R4 resubmit (R4 bench was an infra failure: container broke twice;
// no kernel signal). 4 samples per thread. R3 profile showed L1(LDS)=86.7%
// binding with fma=43.3%: each coefficient LDS.128 fed only 4 FMAs. Amortizing
// each load across 4 samples' accumulators moves the bottleneck to FMA/issue.
// Coefficient reads stay asm volatile (un-hoistable; R1/R2 spilled 1792 B/thr
// when ptxas hoisted the table across the step loop).

#define LATENT 16
#define NFEAT 169
#define NSTEPS 10
#define DT_F 0.01f
#define SPT 4      // samples per thread
#define BLOCK 128

__host__ __device__ __forceinline__ constexpr int quad_row(int i, int j) {
    return 17 + 16 * i - (i * (i - 1)) / 2 + (j - i);
}

__device__ __forceinline__ void lds4(uint32_t addr, float& a, float& b, float& c, float& d) {
    asm volatile("ld.shared.v4.f32 {%0, %1, %2, %3}, [%4];"
                 : "=f"(a), "=f"(b), "=f"(c), "=f"(d) : "r"(addr));
}

__global__ __launch_bounds__(BLOCK) void sindy_shred_kernel(
    const float* __restrict__ h_t,
    const float* __restrict__ coef,
    const float* __restrict__ mask,
    float* __restrict__ out,
    int n, int nrep)
{
    __shared__ float sC[NFEAT * LATENT];

    const int r = blockIdx.y;
    {
        const float* cbase = coef + (size_t)r * NFEAT * LATENT;
        const float* mbase = mask + (size_t)r * NFEAT * LATENT;
        for (int idx = threadIdx.x; idx < NFEAT * LATENT; idx += BLOCK)
            sC[idx] = cbase[idx] * mbase[idx];
    }
    __syncthreads();

    const uint32_t sbase = (uint32_t)__cvta_generic_to_shared(sC);

    // Samples handled by this thread: base + k*BLOCK (k=0..3), coalesced.
    const int base = blockIdx.x * (BLOCK * SPT) + threadIdx.x;
    int  smp[SPT];
    bool val[SPT];
    #pragma unroll
    for (int k = 0; k < SPT; k++) {
        smp[k] = base + k * BLOCK;
        val[k] = smp[k] < n;
    }

    float z[SPT][LATENT];
    #pragma unroll
    for (int k = 0; k < SPT; k++) {
        if (val[k]) {
            const float4* hp = reinterpret_cast<const float4*>(h_t + (size_t)smp[k] * LATENT);
            #pragma unroll
            for (int q = 0; q < 4; q++) {
                float4 v = hp[q];
                z[k][4*q+0] = v.x; z[k][4*q+1] = v.y;
                z[k][4*q+2] = v.z; z[k][4*q+3] = v.w;
            }
        } else {
            #pragma unroll
            for (int d = 0; d < LATENT; d++) z[k][d] = 0.0f;
        }
    }

    float acc[SPT][LATENT];

    // Apply one feature row (given per-sample theta values t[k]) to all accs.
    auto do_row = [&](uint32_t rowbase, const float (&t)[SPT]) {
        #pragma unroll
        for (int q = 0; q < 4; q++) {
            float c0, c1, c2, c3;
            lds4(rowbase + (uint32_t)q * 16u, c0, c1, c2, c3);
            #pragma unroll
            for (int k = 0; k < SPT; k++) {
                acc[k][4*q+0] = fmaf(t[k], c0, acc[k][4*q+0]);
                acc[k][4*q+1] = fmaf(t[k], c1, acc[k][4*q+1]);
                acc[k][4*q+2] = fmaf(t[k], c2, acc[k][4*q+2]);
                acc[k][4*q+3] = fmaf(t[k], c3, acc[k][4*q+3]);
            }
        }
    };

    #pragma unroll 1
    for (int s = 0; s < NSTEPS; s++) {
        // row 0: constant feature -> acc = C[0][:]
        #pragma unroll
        for (int q = 0; q < 4; q++) {
            float c0, c1, c2, c3;
            lds4(sbase + (uint32_t)q * 16u, c0, c1, c2, c3);
            #pragma unroll
            for (int k = 0; k < SPT; k++) {
                acc[k][4*q+0] = c0; acc[k][4*q+1] = c1;
                acc[k][4*q+2] = c2; acc[k][4*q+3] = c3;
            }
        }

        // rows 1..16: linear, theta = z_i
        #pragma unroll
        for (int i = 0; i < LATENT; i++) {
            float t[SPT];
            #pragma unroll
            for (int k = 0; k < SPT; k++) t[k] = z[k][i];
            do_row(sbase + (uint32_t)(1 + i) * 64u, t);
        }

        // rows 17..152: quadratic, theta = z_i * z_j (i<=j)
        #pragma unroll
        for (int i = 0; i < LATENT; i++) {
            #pragma unroll
            for (int j = i; j < LATENT; j++) {
                float t[SPT];
                #pragma unroll
                for (int k = 0; k < SPT; k++) t[k] = z[k][i] * z[k][j];
                do_row(sbase + (uint32_t)quad_row(i, j) * 64u, t);
            }
        }

        // rows 153..168: sine, theta = sin(z_i)
        #pragma unroll
        for (int i = 0; i < LATENT; i++) {
            float t[SPT];
            #pragma unroll
            for (int k = 0; k < SPT; k++) t[k] = __sinf(z[k][i]);
            do_row(sbase + (uint32_t)(153 + i) * 64u, t);
        }

        // Euler update: z += dz * dt
        #pragma unroll
        for (int k = 0; k < SPT; k++)
            #pragma unroll
            for (int d = 0; d < LATENT; d++)
                z[k][d] = fmaf(acc[k][d], DT_F, z[k][d]);
    }

    // out layout: [n, nrep, 16]
    #pragma unroll
    for (int k = 0; k < SPT; k++) {
        if (val[k]) {
            float4* op = reinterpret_cast<float4*>(out + ((size_t)smp[k] * nrep + r) * LATENT);
            #pragma unroll
            for (int q = 0; q < 4; q++) {
                float4 v;
                v.x = z[k][4*q+0]; v.y = z[k][4*q+1];
                v.z = z[k][4*q+2]; v.w = z[k][4*q+3];
                op[q] = v;
            }
        }
    }
}

extern "C" void kernel_launch(void* const* d_in, const int* in_sizes, int n_in,
                              void* d_out, int out_size) {
    const float* h_t  = (const float*)d_in[0];
    const float* coef = (const float*)d_in[1];
    const float* mask = (const float*)d_in[2];
    float* out = (float*)d_out;

    int n    = in_sizes[0] / LATENT;            // samples
    int nrep = in_sizes[1] / (NFEAT * LATENT);  // replicates

    dim3 block(BLOCK);
    dim3 grid((n + BLOCK * SPT - 1) / (BLOCK * SPT), nrep);
    sindy_shred_kernel<<<grid, block>>>(h_t, coef, mask, out, n, nrep);
}

// round 8
// speedup vs baseline: 2.0678x; 2.0678x over previous
#include <cuda_runtime.h>
#include <cstdint>

// SINDy_SHRED: 10 Euler steps of z += Theta(z) @ (C*mask) * dt
// per (sample, replicate). Theta = [1, z, z_i z_j (i<=j), sin(z)] -> 169 rows.
//
// R8: tcgen05 is impossible (harness ptxas target is plain sm_100; R7 proved
// it rejects tcgen05). Best vector path: SPT=2 samples/thread + packed
// fma.rn.f32x2 accumulation (accepted on sm_100 -- R1 compiled).
//  - LDS floor: ~2 SM-cyc per broadcast LDS.128 (R3 calibration) -> 676/2
//    loads per warp-step -> ~385us.
//  - FMA floor with f32x2: ~190us. Predict ~400-460us, L1-bound.
// Coefficient loads via asm volatile ld.shared.v2.u64 (un-hoistable; R1/R2
// spilled 1792B/thread when ptxas hoisted the SMEM table across the loop).
// __launch_bounds__(256,2) caps regs at 128 -> no spill, 16 warps/SM.

#define LATENT 16
#define NFEAT 169
#define NSTEPS 10
#define DT_F 0.01f
#define SPT 2
#define BLOCK 256

typedef unsigned long long u64;

__host__ __device__ __forceinline__ constexpr int quad_row(int i, int j) {
    return 17 + 16 * i - (i * (i - 1)) / 2 + (j - i);
}

__device__ __forceinline__ void lds_v2u64(uint32_t addr, u64& a, u64& b) {
    asm volatile("ld.shared.v2.u64 {%0, %1}, [%2];"
                 : "=l"(a), "=l"(b) : "r"(addr));
}
__device__ __forceinline__ u64 pack2(float x) {
    u64 r; asm("mov.b64 %0, {%1, %1};" : "=l"(r) : "f"(x)); return r;
}
__device__ __forceinline__ void unpack2(u64 v, float& lo, float& hi) {
    asm("mov.b64 {%0, %1}, %2;" : "=f"(lo), "=f"(hi) : "l"(v));
}
__device__ __forceinline__ u64 ffma2(u64 a, u64 b, u64 c) {
    u64 d; asm("fma.rn.f32x2 %0, %1, %2, %3;" : "=l"(d) : "l"(a), "l"(b), "l"(c)); return d;
}

__global__ __launch_bounds__(BLOCK, 2) void sindy_shred_kernel(
    const float* __restrict__ h_t,
    const float* __restrict__ coef,
    const float* __restrict__ mask,
    float* __restrict__ out,
    int n, int nrep)
{
    // Masked coefficients, row-major [169][16] f32. u64 reads see (c[d],c[d+1]).
    __shared__ __align__(16) float sC[NFEAT * LATENT];

    const int r = blockIdx.y;
    {
        const float* cbase = coef + (size_t)r * NFEAT * LATENT;
        const float* mbase = mask + (size_t)r * NFEAT * LATENT;
        for (int idx = threadIdx.x; idx < NFEAT * LATENT; idx += BLOCK)
            sC[idx] = cbase[idx] * mbase[idx];
    }
    __syncthreads();

    const uint32_t sbase = (uint32_t)__cvta_generic_to_shared(sC);

    const int base = blockIdx.x * (BLOCK * SPT) + threadIdx.x;
    int  smp[SPT];
    bool val[SPT];
    #pragma unroll
    for (int k = 0; k < SPT; k++) {
        smp[k] = base + k * BLOCK;
        val[k] = smp[k] < n;
    }

    float z0[LATENT], z1[LATENT];
    #pragma unroll
    for (int d = 0; d < LATENT; d++) { z0[d] = 0.0f; z1[d] = 0.0f; }
    if (val[0]) {
        const float4* hp = reinterpret_cast<const float4*>(h_t + (size_t)smp[0] * LATENT);
        #pragma unroll
        for (int q = 0; q < 4; q++) {
            float4 v = hp[q];
            z0[4*q+0] = v.x; z0[4*q+1] = v.y; z0[4*q+2] = v.z; z0[4*q+3] = v.w;
        }
    }
    if (val[1]) {
        const float4* hp = reinterpret_cast<const float4*>(h_t + (size_t)smp[1] * LATENT);
        #pragma unroll
        for (int q = 0; q < 4; q++) {
            float4 v = hp[q];
            z1[4*q+0] = v.x; z1[4*q+1] = v.y; z1[4*q+2] = v.z; z1[4*q+3] = v.w;
        }
    }

    // acc0/acc1: 8 u64 each = 16 dims as f32x2 pairs
    u64 acc0[8], acc1[8];

    // one feature row: t0/t1 = splatted theta for the two samples
    auto do_row = [&](uint32_t rowbase, u64 t0, u64 t1) {
        #pragma unroll
        for (int h = 0; h < 4; h++) {
            u64 c0, c1;
            lds_v2u64(rowbase + (uint32_t)h * 16u, c0, c1);
            acc0[2*h+0] = ffma2(t0, c0, acc0[2*h+0]);
            acc0[2*h+1] = ffma2(t0, c1, acc0[2*h+1]);
            acc1[2*h+0] = ffma2(t1, c0, acc1[2*h+0]);
            acc1[2*h+1] = ffma2(t1, c1, acc1[2*h+1]);
        }
    };

    #pragma unroll 1
    for (int s = 0; s < NSTEPS; s++) {
        // row 0: constant feature -> acc = C[0][:]
        #pragma unroll
        for (int h = 0; h < 4; h++) {
            u64 c0, c1;
            lds_v2u64(sbase + (uint32_t)h * 16u, c0, c1);
            acc0[2*h+0] = c0; acc0[2*h+1] = c1;
            acc1[2*h+0] = c0; acc1[2*h+1] = c1;
        }

        // rows 1..16: linear, theta = z_i
        #pragma unroll
        for (int i = 0; i < LATENT; i++)
            do_row(sbase + (uint32_t)(1 + i) * 64u, pack2(z0[i]), pack2(z1[i]));

        // rows 17..152: quadratic, theta = z_i * z_j (i<=j)
        #pragma unroll
        for (int i = 0; i < LATENT; i++) {
            #pragma unroll
            for (int j = i; j < LATENT; j++)
                do_row(sbase + (uint32_t)quad_row(i, j) * 64u,
                       pack2(z0[i] * z0[j]), pack2(z1[i] * z1[j]));
        }

        // rows 153..168: sine, theta = sin(z_i)
        #pragma unroll
        for (int i = 0; i < LATENT; i++)
            do_row(sbase + (uint32_t)(153 + i) * 64u,
                   pack2(__sinf(z0[i])), pack2(__sinf(z1[i])));

        // Euler update: z += dz * dt
        #pragma unroll
        for (int p = 0; p < 8; p++) {
            float lo, hi;
            unpack2(acc0[p], lo, hi);
            z0[2*p+0] = fmaf(lo, DT_F, z0[2*p+0]);
            z0[2*p+1] = fmaf(hi, DT_F, z0[2*p+1]);
            unpack2(acc1[p], lo, hi);
            z1[2*p+0] = fmaf(lo, DT_F, z1[2*p+0]);
            z1[2*p+1] = fmaf(hi, DT_F, z1[2*p+1]);
        }
    }

    // out layout: [n, nrep, 16]
    if (val[0]) {
        float4* op = reinterpret_cast<float4*>(out + ((size_t)smp[0] * nrep + r) * LATENT);
        #pragma unroll
        for (int q = 0; q < 4; q++) {
            float4 v;
            v.x = z0[4*q+0]; v.y = z0[4*q+1]; v.z = z0[4*q+2]; v.w = z0[4*q+3];
            op[q] = v;
        }
    }
    if (val[1]) {
        float4* op = reinterpret_cast<float4*>(out + ((size_t)smp[1] * nrep + r) * LATENT);
        #pragma unroll
        for (int q = 0; q < 4; q++) {
            float4 v;
            v.x = z1[4*q+0]; v.y = z1[4*q+1]; v.z = z1[4*q+2]; v.w = z1[4*q+3];
            op[q] = v;
        }
    }
}

extern "C" void kernel_launch(void* const* d_in, const int* in_sizes, int n_in,
                              void* d_out, int out_size) {
    const float* h_t  = (const float*)d_in[0];
    const float* coef = (const float*)d_in[1];
    const float* mask = (const float*)d_in[2];
    float* out = (float*)d_out;

    int n    = in_sizes[0] / LATENT;            // samples
    int nrep = in_sizes[1] / (NFEAT * LATENT);  // replicates

    dim3 block(BLOCK);
    dim3 grid((n + BLOCK * SPT - 1) / (BLOCK * SPT), nrep);
    sindy_shred_kernel<<<grid, block>>>(h_t, coef, mask, out, n, nrep);
}

// round 9
// speedup vs baseline: 6.2754x; 3.0348x over previous
#include <cuda_runtime.h>
#include <cuda_bf16.h>
#include <cstdint>

// SINDy_SHRED via warp-level bf16 HMMA (mma.sync.m16n8k16 -- sm_80+ feature,
// compiles on the harness's plain sm_100 target unlike tcgen05).
//
// Per warp: 32 samples. Each thread owns sample = warp_base + lane:
//  - builds full theta row (169 feats, f32, templated) -> bf16x2 -> SMEM tile
//  - ldmatrix.x4 loads A fragments (2 m16 tiles), 44 HMMA/step vs coeff B
//    fragments (44 regs, built once from the masked table)
//  - dz round-trips via padded SMEM tile; z updated in fp32 registers.
// R8 calibration: fp32 pipe caps this problem at ~384us (FFMA rt=1, FFMA2
// rt=2 -> same flops). HMMA moves the 169x16 matvec off the fp32 pipe.

#define LATENT 16
#define NFEAT 169
#define NSTEPS 10
#define DT_F 0.01f
#define KSTEPS 11            // 11*16 = 176 features (169 used, pad zero)
#define WARPS 8
#define BLOCK (WARPS * 32)
#define SPW 32               // samples per warp
#define SAMPLES_CTA (WARPS * SPW)
#define NFPAD 176            // padded feature rows in coeff table

#define TH_STRIDE 48u        // theta tile row stride (bytes): conflict-free ldmatrix
#define TH_BUF 1536u         // 32 rows * 48B, double-buffered
#define WREGION 3072u        // per-warp smem region (2 theta bufs; dz unioned)
#define DZ_STRIDE 80u        // dz tile row stride (bytes), padded

// ---------- helpers ----------
__device__ __forceinline__ uint32_t smem_u32(const void* p) {
    return (uint32_t)__cvta_generic_to_shared(p);
}
__device__ __forceinline__ uint32_t cvt_bf16x2(float hi, float lo) {
    uint32_t r;
    asm("cvt.rn.bf16x2.f32 %0, %1, %2;" : "=r"(r) : "f"(hi), "f"(lo));
    return r;
}
__device__ __forceinline__ void sts128(uint32_t a, uint32_t x, uint32_t y, uint32_t z, uint32_t w) {
    asm volatile("st.shared.v4.b32 [%0], {%1,%2,%3,%4};"
                 :: "r"(a), "r"(x), "r"(y), "r"(z), "r"(w) : "memory");
}
__device__ __forceinline__ void sts64f(uint32_t a, float x, float y) {
    asm volatile("st.shared.v2.f32 [%0], {%1,%2};" :: "r"(a), "f"(x), "f"(y) : "memory");
}
__device__ __forceinline__ void lds128f(uint32_t a, float& x, float& y, float& z, float& w) {
    asm volatile("ld.shared.v4.f32 {%0,%1,%2,%3}, [%4];"
                 : "=f"(x), "=f"(y), "=f"(z), "=f"(w) : "r"(a));
}
__device__ __forceinline__ void ldsm4(uint32_t* a, uint32_t addr) {
    asm volatile("ldmatrix.sync.aligned.m8n8.x4.shared.b16 {%0,%1,%2,%3}, [%4];"
                 : "=r"(a[0]), "=r"(a[1]), "=r"(a[2]), "=r"(a[3]) : "r"(addr));
}
__device__ __forceinline__ void mma16816(float* d, const uint32_t* a, const uint32_t* b) {
    asm volatile(
        "mma.sync.aligned.m16n8k16.row.col.f32.bf16.bf16.f32 "
        "{%0,%1,%2,%3}, {%4,%5,%6,%7}, {%8,%9}, {%0,%1,%2,%3};"
        : "+f"(d[0]), "+f"(d[1]), "+f"(d[2]), "+f"(d[3])
        : "r"(a[0]), "r"(a[1]), "r"(a[2]), "r"(a[3]), "r"(b[0]), "r"(b[1]));
}

// ---------- compile-time theta mapping ----------
struct QP { int i, j; };
__host__ __device__ constexpr QP quad_pair_ce(int q) {
    int i = 0, rem = q;
    while (rem >= 16 - i) { rem -= 16 - i; i++; }
    return QP{i, i + rem};
}
template <int T>
__device__ __forceinline__ float theta_t(const float* z) {
    if constexpr (T == 0) return 1.0f;
    else if constexpr (T < 17) return z[T - 1];
    else if constexpr (T < 153) {
        constexpr QP p = quad_pair_ce(T - 17);
        return z[p.i] * z[p.j];
    } else if constexpr (T < 169) return __sinf(z[T - 153]);
    else return 0.0f;
}
template <int C0, int N>
__device__ __forceinline__ void build_cols(uint32_t* a, const float* z) {
    if constexpr (N > 0) {
        a[0] = cvt_bf16x2(theta_t<2 * C0 + 1>(z), theta_t<2 * C0>(z)); // hi, lo
        build_cols<C0 + 1, N - 1>(a + 1, z);
    }
}

// one k-step: build theta cols K*16..K*16+15, STS, ldmatrix both m-tiles, 4 HMMA
template <int K>
__device__ __forceinline__ void run_ksteps(
    const float* z, const uint32_t (&B)[KSTEPS][2][2], float (&D)[2][2][4],
    uint32_t st_addr, uint32_t lm0, uint32_t lm1)
{
    if constexpr (K < KSTEPS) {
        uint32_t th[8];
        build_cols<K * 8, 8>(th, z);
        constexpr uint32_t buf = (K & 1) ? TH_BUF : 0u;
        sts128(st_addr + buf,      th[0], th[1], th[2], th[3]);
        sts128(st_addr + buf + 16, th[4], th[5], th[6], th[7]);
        __syncwarp();
        uint32_t a[4];
        ldsm4(a, lm0 + buf);
        mma16816(D[0][0], a, B[K][0]);
        mma16816(D[0][1], a, B[K][1]);
        ldsm4(a, lm1 + buf);
        mma16816(D[1][0], a, B[K][0]);
        mma16816(D[1][1], a, B[K][1]);
        run_ksteps<K + 1>(z, B, D, st_addr, lm0, lm1);
    }
}

// ---------- kernel ----------
__global__ __launch_bounds__(BLOCK, 2) void sindy_shred_hmma_kernel(
    const float* __restrict__ h_t,
    const float* __restrict__ coef,
    const float* __restrict__ mask,
    float* __restrict__ out,
    int n, int nrep)
{
    __shared__ __align__(16) float sC[NFPAD * LATENT];        // masked coeffs, padded
    __shared__ __align__(16) uint8_t swork[WARPS * WREGION];  // per-warp theta/dz tiles

    const int tid  = threadIdx.x;
    const int lane = tid & 31;
    const int warp = tid >> 5;
    const int r    = blockIdx.y;

    {
        const float* cbase = coef + (size_t)r * NFEAT * LATENT;
        const float* mbase = mask + (size_t)r * NFEAT * LATENT;
        for (int idx = tid; idx < NFPAD * LATENT; idx += BLOCK)
            sC[idx] = (idx < NFEAT * LATENT) ? cbase[idx] * mbase[idx] : 0.0f;
    }
    __syncthreads();

    // B fragments: thread holds C[k][n] for n = lane/4, k = 2c,2c+1 (+8) per kstep.
    const int c4 = lane & 3, g = lane >> 2;
    uint32_t B[KSTEPS][2][2];
    #pragma unroll
    for (int k = 0; k < KSTEPS; k++) {
        const int f0 = k * 16 + c4 * 2;
        #pragma unroll
        for (int nt = 0; nt < 2; nt++) {
            const int nn = nt * 8 + g;
            B[k][nt][0] = cvt_bf16x2(sC[(f0 + 1) * LATENT + nn], sC[(f0 + 0) * LATENT + nn]);
            B[k][nt][1] = cvt_bf16x2(sC[(f0 + 9) * LATENT + nn], sC[(f0 + 8) * LATENT + nn]);
        }
    }

    const uint32_t wbase   = smem_u32(swork + (size_t)warp * WREGION);
    const uint32_t st_addr = wbase + (uint32_t)lane * TH_STRIDE;
    const uint32_t lm0     = wbase + (uint32_t)(lane & 15) * TH_STRIDE + (uint32_t)(lane >> 4) * 16u;
    const uint32_t lm1     = lm0 + 16u * TH_STRIDE;

    const int sample = blockIdx.x * SAMPLES_CTA + warp * SPW + lane;
    const bool valid = sample < n;

    float z[LATENT];
    #pragma unroll
    for (int d = 0; d < LATENT; d++) z[d] = 0.0f;
    if (valid) {
        const float4* hp = reinterpret_cast<const float4*>(h_t + (size_t)sample * LATENT);
        #pragma unroll
        for (int q = 0; q < 4; q++) {
            float4 v = hp[q];
            z[4*q+0] = v.x; z[4*q+1] = v.y; z[4*q+2] = v.z; z[4*q+3] = v.w;
        }
    }

    #pragma unroll 1
    for (int s = 0; s < NSTEPS; s++) {
        float D[2][2][4];
        #pragma unroll
        for (int mt = 0; mt < 2; mt++)
            #pragma unroll
            for (int nt = 0; nt < 2; nt++)
                #pragma unroll
                for (int e = 0; e < 4; e++) D[mt][nt][e] = 0.0f;

        run_ksteps<0>(z, B, D, st_addr, lm0, lm1);

        __syncwarp();   // last ldmatrix reads done before dz overwrites region
        #pragma unroll
        for (int mt = 0; mt < 2; mt++) {
            #pragma unroll
            for (int nt = 0; nt < 2; nt++) {
                uint32_t a0 = wbase + (uint32_t)(g + mt * 16) * DZ_STRIDE
                                    + (uint32_t)(nt * 8 + c4 * 2) * 4u;
                sts64f(a0,                   D[mt][nt][0], D[mt][nt][1]);
                sts64f(a0 + 8u * DZ_STRIDE,  D[mt][nt][2], D[mt][nt][3]);
            }
        }
        __syncwarp();
        float dz[LATENT];
        #pragma unroll
        for (int q = 0; q < 4; q++)
            lds128f(wbase + (uint32_t)lane * DZ_STRIDE + (uint32_t)q * 16u,
                    dz[4*q+0], dz[4*q+1], dz[4*q+2], dz[4*q+3]);
        #pragma unroll
        for (int d = 0; d < LATENT; d++)
            z[d] = fmaf(dz[d], DT_F, z[d]);
        __syncwarp();   // dz reads done before next step's theta STS
    }

    if (valid) {
        float4* op = reinterpret_cast<float4*>(out + ((size_t)sample * nrep + r) * LATENT);
        #pragma unroll
        for (int q = 0; q < 4; q++) {
            float4 v;
            v.x = z[4*q+0]; v.y = z[4*q+1]; v.z = z[4*q+2]; v.w = z[4*q+3];
            op[q] = v;
        }
    }
}

extern "C" void kernel_launch(void* const* d_in, const int* in_sizes, int n_in,
                              void* d_out, int out_size) {
    const float* h_t  = (const float*)d_in[0];
    const float* coef = (const float*)d_in[1];
    const float* mask = (const float*)d_in[2];
    float* out = (float*)d_out;

    int n    = in_sizes[0] / LATENT;            // samples
    int nrep = in_sizes[1] / (NFEAT * LATENT);  // replicates

    dim3 block(BLOCK);
    dim3 grid((n + SAMPLES_CTA - 1) / SAMPLES_CTA, nrep);
    sindy_shred_hmma_kernel<<<grid, block>>>(h_t, coef, mask, out, n, nrep);
}